// round 17
// baseline (speedup 1.0000x reference)
#include <cuda_runtime.h>
#include <math.h>

#define NROWS 8192
#define F     512
#define NCLS  8
#define ELLW  192

// ---------------- static scratch (device globals; no runtime alloc) ----------
__device__ __align__(16) float g_XW[NROWS * F];   // x@W1 ; later reused as Xpre
__device__ __align__(16) float g_h [NROWS * F];
__device__ __align__(16) float g_R [NROWS * F];   // R' = h @ M
__device__ __align__(16) float g_V [NROWS * F];   // T = Xpre@Vw + Vb
__device__ __align__(16) float g_Y [NROWS * NCLS];
__device__ __align__(16) float g_N [F * F];       // M = Qw @ Kw^T
__device__ __align__(16) float g_u [F];           // u = Qw @ Kb
__device__ __align__(16) float g_v [F];           // v = Kw @ Qb
__device__ float g_c;                             // c = Qb . Kb
__device__ float g_bv[NROWS];                     // b_j = h_j . v
__device__ float g_av[NROWS];                     // a_i = h_i . u
__device__ int   g_col[NROWS * ELLW];
__device__ int   g_len[NROWS];
__device__ __align__(16) float g_csum[F];         // column sums of h
__device__ float g_part[32 * F];

// ---------------- packed f32x2 helpers (Blackwell FFMA2 path) ----------------
__device__ __forceinline__ unsigned long long pk2(float x, float y) {
    unsigned long long r;
    asm("mov.b64 %0, {%1, %2};" : "=l"(r) : "f"(x), "f"(y));
    return r;
}
__device__ __forceinline__ float2 upk2(unsigned long long v) {
    float2 r;
    asm("mov.b64 {%0, %1}, %2;" : "=f"(r.x), "=f"(r.y) : "l"(v));
    return r;
}
__device__ __forceinline__ void fma2(unsigned long long& d,
                                     unsigned long long a,
                                     unsigned long long b) {
    asm("fma.rn.f32x2 %0, %1, %2, %0;" : "+l"(d) : "l"(a), "l"(b));
}

// ---------------- 1. adjacency -> ELL (warp/row, MLP=4, ballot compaction) ---
__global__ __launch_bounds__(128) void build_ell(const float* __restrict__ adj) {
    int warp_id = blockIdx.x * (blockDim.x >> 5) + (threadIdx.x >> 5);
    if (warp_id >= NROWS) return;
    int lane = threadIdx.x & 31;
    const float* ar = adj + (size_t)warp_id * NROWS;
    int cnt = 0;
    int* crow = g_col + warp_id * ELLW;
    for (int b = 0; b < NROWS; b += 128) {
        float v0 = ar[b + lane];
        float v1 = ar[b + 32 + lane];
        float v2 = ar[b + 64 + lane];
        float v3 = ar[b + 96 + lane];
        unsigned m0 = __ballot_sync(0xFFFFFFFFu, v0 != 0.0f);
        unsigned m1 = __ballot_sync(0xFFFFFFFFu, v1 != 0.0f);
        unsigned m2 = __ballot_sync(0xFFFFFFFFu, v2 != 0.0f);
        unsigned m3 = __ballot_sync(0xFFFFFFFFu, v3 != 0.0f);
        unsigned lm = (1u << lane) - 1u;
        if (v0 != 0.0f) { int p = cnt + __popc(m0 & lm); if (p < ELLW) crow[p] = b + lane; }
        cnt += __popc(m0);
        if (v1 != 0.0f) { int p = cnt + __popc(m1 & lm); if (p < ELLW) crow[p] = b + 32 + lane; }
        cnt += __popc(m1);
        if (v2 != 0.0f) { int p = cnt + __popc(m2 & lm); if (p < ELLW) crow[p] = b + 64 + lane; }
        cnt += __popc(m2);
        if (v3 != 0.0f) { int p = cnt + __popc(m3 & lm); if (p < ELLW) crow[p] = b + 96 + lane; }
        cnt += __popc(m3);
    }
    if (lane == 0) g_len[warp_id] = cnt < ELLW ? cnt : ELLW;
}

// ---------------- 2. fp32 SGEMM with packed FFMA2 (champion) -----------------
__global__ __launch_bounds__(256, 2) void sgemm512(const float* __restrict__ A,
                                                   const float* __restrict__ B,
                                                   const float* __restrict__ bias,
                                                   float* __restrict__ C) {
    __shared__ float As[2][16][132];
    __shared__ float Bs[2][16][128];
    const int tid = threadIdx.x;
    const int bm = blockIdx.y, bn = blockIdx.x;
    const float* Ab = A + (size_t)bm * 128 * F;
    const float* Bb = B + bn * 128;

    const int arow = tid >> 2, acol = (tid & 3) << 2;
    const int brow = tid >> 5, bcol = (tid & 31) << 2;
    const int tx = tid & 15, ty = tid >> 4;

    float4 pa0, pa1, pb0, pb1;
    pa0 = *(const float4*)(Ab + (size_t)arow * F + acol);
    pa1 = *(const float4*)(Ab + (size_t)(arow + 64) * F + acol);
    pb0 = *(const float4*)(Bb + (size_t)brow * F + bcol);
    pb1 = *(const float4*)(Bb + (size_t)(brow + 8) * F + bcol);

    unsigned long long acc[4][8];
#pragma unroll
    for (int ip = 0; ip < 4; ip++)
#pragma unroll
        for (int j = 0; j < 8; j++) acc[ip][j] = 0ULL;

    As[0][acol + 0][arow] = pa0.x; As[0][acol + 1][arow] = pa0.y;
    As[0][acol + 2][arow] = pa0.z; As[0][acol + 3][arow] = pa0.w;
    As[0][acol + 0][arow + 64] = pa1.x; As[0][acol + 1][arow + 64] = pa1.y;
    As[0][acol + 2][arow + 64] = pa1.z; As[0][acol + 3][arow + 64] = pa1.w;
    *(float4*)(&Bs[0][brow][bcol])     = pb0;
    *(float4*)(&Bs[0][brow + 8][bcol]) = pb1;
    __syncthreads();

    int buf = 0;
#pragma unroll 1
    for (int kt = 16; kt <= F; kt += 16) {
        if (kt < F) {
            pa0 = *(const float4*)(Ab + (size_t)arow * F + kt + acol);
            pa1 = *(const float4*)(Ab + (size_t)(arow + 64) * F + kt + acol);
            pb0 = *(const float4*)(Bb + (size_t)(kt + brow) * F + bcol);
            pb1 = *(const float4*)(Bb + (size_t)(kt + brow + 8) * F + bcol);
        }
#pragma unroll
        for (int k = 0; k < 16; k++) {
            float4 av0 = *(const float4*)(&As[buf][k][ty * 4]);
            float4 av1 = *(const float4*)(&As[buf][k][64 + ty * 4]);
            float4 bv0 = *(const float4*)(&Bs[buf][k][tx * 4]);
            float4 bv1 = *(const float4*)(&Bs[buf][k][64 + tx * 4]);
            unsigned long long ap[4], bd[8];
            ap[0] = pk2(av0.x, av0.y); ap[1] = pk2(av0.z, av0.w);
            ap[2] = pk2(av1.x, av1.y); ap[3] = pk2(av1.z, av1.w);
            bd[0] = pk2(bv0.x, bv0.x); bd[1] = pk2(bv0.y, bv0.y);
            bd[2] = pk2(bv0.z, bv0.z); bd[3] = pk2(bv0.w, bv0.w);
            bd[4] = pk2(bv1.x, bv1.x); bd[5] = pk2(bv1.y, bv1.y);
            bd[6] = pk2(bv1.z, bv1.z); bd[7] = pk2(bv1.w, bv1.w);
#pragma unroll
            for (int ip = 0; ip < 4; ip++)
#pragma unroll
                for (int j = 0; j < 8; j++) fma2(acc[ip][j], ap[ip], bd[j]);
        }
        if (kt < F) {
            int nb = buf ^ 1;
            As[nb][acol + 0][arow] = pa0.x; As[nb][acol + 1][arow] = pa0.y;
            As[nb][acol + 2][arow] = pa0.z; As[nb][acol + 3][arow] = pa0.w;
            As[nb][acol + 0][arow + 64] = pa1.x; As[nb][acol + 1][arow + 64] = pa1.y;
            As[nb][acol + 2][arow + 64] = pa1.z; As[nb][acol + 3][arow + 64] = pa1.w;
            *(float4*)(&Bs[nb][brow][bcol])     = pb0;
            *(float4*)(&Bs[nb][brow + 8][bcol]) = pb1;
            __syncthreads();
            buf = nb;
        }
    }

    float bb[8];
#pragma unroll
    for (int j = 0; j < 4; j++) {
        bb[j]     = bias ? bias[bn * 128 + tx * 4 + j]      : 0.0f;
        bb[4 + j] = bias ? bias[bn * 128 + 64 + tx * 4 + j] : 0.0f;
    }
#pragma unroll
    for (int ip = 0; ip < 4; ip++) {
        int rbase = (ip < 2) ? (ty * 4 + 2 * ip) : (64 + ty * 4 + 2 * (ip - 2));
        float2 c[8];
#pragma unroll
        for (int j = 0; j < 8; j++) c[j] = upk2(acc[ip][j]);
        {
            int row = bm * 128 + rbase;
            float* Cr = C + (size_t)row * F + bn * 128;
            float4 v0 = make_float4(c[0].x + bb[0], c[1].x + bb[1],
                                    c[2].x + bb[2], c[3].x + bb[3]);
            float4 v1 = make_float4(c[4].x + bb[4], c[5].x + bb[5],
                                    c[6].x + bb[6], c[7].x + bb[7]);
            *(float4*)(Cr + tx * 4)      = v0;
            *(float4*)(Cr + 64 + tx * 4) = v1;
        }
        {
            int row = bm * 128 + rbase + 1;
            float* Cr = C + (size_t)row * F + bn * 128;
            float4 v0 = make_float4(c[0].y + bb[0], c[1].y + bb[1],
                                    c[2].y + bb[2], c[3].y + bb[3]);
            float4 v1 = make_float4(c[4].y + bb[4], c[5].y + bb[5],
                                    c[6].y + bb[6], c[7].y + bb[7]);
            *(float4*)(Cr + tx * 4)      = v0;
            *(float4*)(Cr + 64 + tx * 4) = v1;
        }
    }
}

// ---------------- 2b. M = Qw @ Kw^T ------------------------------------------
__global__ __launch_bounds__(256) void gemm_abt512(const float* __restrict__ A,
                                                   const float* __restrict__ B,
                                                   float* __restrict__ C) {
    __shared__ float As[64][33];
    __shared__ float Bs[64][33];
    const int t = threadIdx.x;
    const int tx = t & 15, ty = t >> 4;
    const int m0 = blockIdx.y * 64, n0 = blockIdx.x * 64;
    float acc[4][4];
#pragma unroll
    for (int i = 0; i < 4; i++)
#pragma unroll
        for (int j = 0; j < 4; j++) acc[i][j] = 0.0f;

    for (int kt = 0; kt < F; kt += 32) {
#pragma unroll
        for (int r = 0; r < 8; r++) {
            int idx = t + r * 256;
            int row = idx >> 5, k = idx & 31;
            As[row][k] = A[(size_t)(m0 + row) * F + kt + k];
            Bs[row][k] = B[(size_t)(n0 + row) * F + kt + k];
        }
        __syncthreads();
#pragma unroll
        for (int k = 0; k < 32; k++) {
            float a[4], b[4];
#pragma unroll
            for (int i = 0; i < 4; i++) a[i] = As[ty * 4 + i][k];
#pragma unroll
            for (int j = 0; j < 4; j++) b[j] = Bs[tx * 4 + j][k];
#pragma unroll
            for (int i = 0; i < 4; i++)
#pragma unroll
                for (int j = 0; j < 4; j++) acc[i][j] = fmaf(a[i], b[j], acc[i][j]);
        }
        __syncthreads();
    }
#pragma unroll
    for (int i = 0; i < 4; i++)
#pragma unroll
        for (int j = 0; j < 4; j++)
            C[(size_t)(m0 + ty * 4 + i) * F + n0 + tx * 4 + j] = acc[i][j];
}

// ---------------- 2c. u = Qw@Kb, v = Kw@Qb, c = Qb.Kb (warp per row) ---------
__global__ __launch_bounds__(256) void uvc_kernel(const float* __restrict__ Qw,
                                                  const float* __restrict__ Qb,
                                                  const float* __restrict__ Kw,
                                                  const float* __restrict__ Kb) {
    int t = threadIdx.x;
    int warp = t >> 5, lane = t & 31;
    int b = blockIdx.x;
    if (b < 128) {
        bool do_u = (b < 64);
        int row = (do_u ? b : b - 64) * 8 + warp;
        const float* W   = do_u ? Qw : Kw;
        const float* vec = do_u ? Kb : Qb;
        const float* wr = W + (size_t)row * F;
        float s = 0.0f;
#pragma unroll 4
        for (int k = lane; k < F; k += 32) s += wr[k] * vec[k];
#pragma unroll
        for (int o = 16; o > 0; o >>= 1) s += __shfl_xor_sync(0xFFFFFFFFu, s, o);
        if (lane == 0) (do_u ? g_u : g_v)[row] = s;
    } else {
        __shared__ float red[256];
        float s = Qb[t] * Kb[t] + Qb[t + 256] * Kb[t + 256];
        red[t] = s;
        __syncthreads();
        for (int o = 128; o > 0; o >>= 1) {
            if (t < o) red[t] += red[t + o];
            __syncthreads();
        }
        if (t == 0) g_c = red[0];
    }
}

// ---------------- 3. h = relu(adj@XW + b), fused a_i=h.u, b_i=h.v ------------
__global__ __launch_bounds__(128) void spmm_relu_bav(const float* __restrict__ XW,
                                                     const float* __restrict__ bias,
                                                     float* __restrict__ H) {
    __shared__ float red[128];
    int row = blockIdx.x, t = threadIdx.x;
    int len = g_len[row];
    const int* cols = g_col + row * ELLW;
    float4 a0 = make_float4(0, 0, 0, 0), a1 = make_float4(0, 0, 0, 0);
    float4 a2 = make_float4(0, 0, 0, 0), a3 = make_float4(0, 0, 0, 0);
    int e = 0;
    for (; e + 3 < len; e += 4) {
        int j0 = __ldg(cols + e),     j1 = __ldg(cols + e + 1);
        int j2 = __ldg(cols + e + 2), j3 = __ldg(cols + e + 3);
        float4 v0 = *(const float4*)(XW + (size_t)j0 * F + (t << 2));
        float4 v1 = *(const float4*)(XW + (size_t)j1 * F + (t << 2));
        float4 v2 = *(const float4*)(XW + (size_t)j2 * F + (t << 2));
        float4 v3 = *(const float4*)(XW + (size_t)j3 * F + (t << 2));
        a0.x += v0.x; a0.y += v0.y; a0.z += v0.z; a0.w += v0.w;
        a1.x += v1.x; a1.y += v1.y; a1.z += v1.z; a1.w += v1.w;
        a2.x += v2.x; a2.y += v2.y; a2.z += v2.z; a2.w += v2.w;
        a3.x += v3.x; a3.y += v3.y; a3.z += v3.z; a3.w += v3.w;
    }
    for (; e < len; e++) {
        int j0 = __ldg(cols + e);
        float4 v0 = *(const float4*)(XW + (size_t)j0 * F + (t << 2));
        a0.x += v0.x; a0.y += v0.y; a0.z += v0.z; a0.w += v0.w;
    }
    float4 b4 = *(const float4*)(bias + (t << 2));
    float4 o;
    o.x = fmaxf((a0.x + a1.x) + (a2.x + a3.x) + b4.x, 0.0f);
    o.y = fmaxf((a0.y + a1.y) + (a2.y + a3.y) + b4.y, 0.0f);
    o.z = fmaxf((a0.z + a1.z) + (a2.z + a3.z) + b4.z, 0.0f);
    o.w = fmaxf((a0.w + a1.w) + (a2.w + a3.w) + b4.w, 0.0f);
    *(float4*)(H + (size_t)row * F + (t << 2)) = o;

    // fused: b_row = h_row . v
    float4 v4 = ((const float4*)g_v)[t];
    red[t] = o.x * v4.x + o.y * v4.y + o.z * v4.z + o.w * v4.w;
    __syncthreads();
    for (int s = 64; s > 0; s >>= 1) {
        if (t < s) red[t] += red[t + s];
        __syncthreads();
    }
    if (t == 0) g_bv[row] = red[0];
    __syncthreads();
    // fused: a_row = h_row . u
    float4 u4 = ((const float4*)g_u)[t];
    red[t] = o.x * u4.x + o.y * u4.y + o.z * u4.z + o.w * u4.w;
    __syncthreads();
    for (int s = 64; s > 0; s >>= 1) {
        if (t < s) red[t] += red[t + s];
        __syncthreads();
    }
    if (t == 0) g_av[row] = red[0];
}

// ---------------- 4. column sums of h ----------------------------------------
__global__ __launch_bounds__(512) void colsum_part(const float* __restrict__ X) {
    int b = blockIdx.x, c = threadIdx.x;
    const float* base = X + (size_t)b * 256 * F + c;
    float s0 = 0, s1 = 0, s2 = 0, s3 = 0;
#pragma unroll 4
    for (int r = 0; r < 256; r += 4) {
        s0 += base[(size_t)(r + 0) * F];
        s1 += base[(size_t)(r + 1) * F];
        s2 += base[(size_t)(r + 2) * F];
        s3 += base[(size_t)(r + 3) * F];
    }
    g_part[b * F + c] = (s0 + s1) + (s2 + s3);
}
__global__ __launch_bounds__(512) void colsum_final() {
    int c = threadIdx.x;
    float s = 0.0f;
#pragma unroll
    for (int b = 0; b < 32; b++) s += g_part[b * F + c];
    g_csum[c] = s;
}

// ---------------- 5. fused attention: Xpre = softmax(adj*(QK)) @ h -----------
__global__ __launch_bounds__(128) void attn_fused(const float* __restrict__ H,
                                                  const float* __restrict__ Rp,
                                                  float* __restrict__ Xp) {
    __shared__ float4 rs[128];
    __shared__ float4 mG[4][128];
    __shared__ float4 mS[4][128];
    __shared__ float wm[4], wh[4];
    int row = blockIdx.x, t = threadIdx.x, lane = t & 31, w = t >> 5;
    rs[t] = ((const float4*)(Rp + (size_t)row * F))[t];
    __syncthreads();

    int len = g_len[row];
    const int* cols = g_col + row * ELLW;
    float abase = g_av[row] + g_c;

    float4 Gm[4], Sh[4];
#pragma unroll
    for (int q = 0; q < 4; q++) {
        Gm[q] = make_float4(0, 0, 0, 0);
        Sh[q] = make_float4(0, 0, 0, 0);
    }
    float m_w = -INFINITY, Hm = 0.0f;

    for (int e = w; e < len; e += 4) {
        int j = __ldg(cols + e);
        const float4* hj = (const float4*)(H + (size_t)j * F);
        float4 hv[4];
#pragma unroll
        for (int q = 0; q < 4; q++) hv[q] = hj[lane + 32 * q];
        float s = 0.0f;
#pragma unroll
        for (int q = 0; q < 4; q++) {
            float4 rv = rs[lane + 32 * q];
            s += hv[q].x * rv.x + hv[q].y * rv.y + hv[q].z * rv.z + hv[q].w * rv.w;
        }
#pragma unroll
        for (int o = 16; o > 0; o >>= 1) s += __shfl_xor_sync(0xFFFFFFFFu, s, o);
        s += abase + __ldg(g_bv + j);

        if (s > m_w) {
            float sc = (m_w == -INFINITY) ? 0.0f : expf(m_w - s);
#pragma unroll
            for (int q = 0; q < 4; q++) {
                Gm[q].x *= sc; Gm[q].y *= sc; Gm[q].z *= sc; Gm[q].w *= sc;
            }
            Hm *= sc;
            m_w = s;
        }
        float we = expf(s - m_w);
        Hm += we;
#pragma unroll
        for (int q = 0; q < 4; q++) {
            Gm[q].x += we * hv[q].x; Gm[q].y += we * hv[q].y;
            Gm[q].z += we * hv[q].z; Gm[q].w += we * hv[q].w;
            Sh[q].x += hv[q].x; Sh[q].y += hv[q].y;
            Sh[q].z += hv[q].z; Sh[q].w += hv[q].w;
        }
    }

    if (lane == 0) { wm[w] = m_w; wh[w] = Hm; }
#pragma unroll
    for (int q = 0; q < 4; q++) {
        mG[w][lane + 32 * q] = Gm[q];
        mS[w][lane + 32 * q] = Sh[q];
    }
    __syncthreads();

    float M = 0.0f;
#pragma unroll
    for (int ww = 0; ww < 4; ww++) M = fmaxf(M, wm[ww]);
    float em = expf(-M);
    float Z = (float)(NROWS - len) * em;
#pragma unroll
    for (int ww = 0; ww < 4; ww++) {
        float hv = wh[ww];
        Z += (hv > 0.0f) ? hv * expf(wm[ww] - M) : 0.0f;
    }

    float4 acc = make_float4(0, 0, 0, 0), sh = make_float4(0, 0, 0, 0);
#pragma unroll
    for (int ww = 0; ww < 4; ww++) {
        float sc = (wh[ww] > 0.0f) ? expf(wm[ww] - M) : 0.0f;
        float4 g = mG[ww][t];
        acc.x += g.x * sc; acc.y += g.y * sc; acc.z += g.z * sc; acc.w += g.w * sc;
        float4 s4 = mS[ww][t];
        sh.x += s4.x; sh.y += s4.y; sh.z += s4.z; sh.w += s4.w;
    }
    float4 cs = ((const float4*)g_csum)[t];
    float invZ = 1.0f / Z;
    float4 o;
    o.x = (acc.x + em * (cs.x - sh.x)) * invZ;
    o.y = (acc.y + em * (cs.y - sh.y)) * invZ;
    o.z = (acc.z + em * (cs.z - sh.z)) * invZ;
    o.w = (acc.w + em * (cs.w - sh.w)) * invZ;
    ((float4*)(Xp + (size_t)row * F))[t] = o;
}

// ---------------- 6. LayerNorm + Y = Xt @ W2 fused (Xt never hits gmem) ------
__global__ __launch_bounds__(128) void ln_ygemm(const float* __restrict__ T,
                                                const float* __restrict__ lng,
                                                const float* __restrict__ lnb,
                                                const float* __restrict__ W2,
                                                float* __restrict__ Y) {
    __shared__ float red[128];
    __shared__ float wred[4][NCLS];
    int row = blockIdx.x, t = threadIdx.x, lane = t & 31, w = t >> 5;
    float4 x = ((const float4*)(T + (size_t)row * F))[t];

    red[t] = x.x + x.y + x.z + x.w;
    __syncthreads();
    for (int s = 64; s > 0; s >>= 1) {
        if (t < s) red[t] += red[t + s];
        __syncthreads();
    }
    float mu = red[0] * (1.0f / F);
    __syncthreads();
    float dx = x.x - mu, dy = x.y - mu, dz = x.z - mu, dw = x.w - mu;
    red[t] = dx * dx + dy * dy + dz * dz + dw * dw;
    __syncthreads();
    for (int s = 64; s > 0; s >>= 1) {
        if (t < s) red[t] += red[t + s];
        __syncthreads();
    }
    float inv = rsqrtf(red[0] * (1.0f / F) + 1e-5f);

    float4 g4 = *(const float4*)(lng + (t << 2));
    float4 b4 = *(const float4*)(lnb + (t << 2));
    float xt0 = dx * inv * g4.x + b4.x;
    float xt1 = dy * inv * g4.y + b4.y;
    float xt2 = dz * inv * g4.z + b4.z;
    float xt3 = dw * inv * g4.w + b4.w;

    // Y[row][c] = sum_k Xt[k] * W2[k][c]; thread holds k = 4t..4t+3.
    const float* w2r = W2 + (size_t)(t << 2) * NCLS;
    float p[NCLS];
#pragma unroll
    for (int c = 0; c < NCLS; c++) {
        p[c] = xt0 * __ldg(w2r + c) + xt1 * __ldg(w2r + NCLS + c) +
               xt2 * __ldg(w2r + 2 * NCLS + c) + xt3 * __ldg(w2r + 3 * NCLS + c);
    }
#pragma unroll
    for (int c = 0; c < NCLS; c++) {
#pragma unroll
        for (int o = 16; o > 0; o >>= 1) p[c] += __shfl_xor_sync(0xFFFFFFFFu, p[c], o);
    }
    if (lane == 0) {
#pragma unroll
        for (int c = 0; c < NCLS; c++) wred[w][c] = p[c];
    }
    __syncthreads();
    if (t < NCLS)
        Y[row * NCLS + t] = (wred[0][t] + wred[1][t]) + (wred[2][t] + wred[3][t]);
}

// ---------------- 8. z = adj @ Y + b2, row softmax ---------------------------
__global__ __launch_bounds__(256) void z_softmax(const float* __restrict__ Y,
                                                 const float* __restrict__ b2,
                                                 float* __restrict__ out) {
    int t = threadIdx.x;
    int row = blockIdx.x * 32 + (t >> 3);
    int c = t & 7;
    int len = g_len[row];
    const int* cols = g_col + row * ELLW;
    float acc = b2[c];
    for (int e = 0; e < len; e++) acc += __ldg(Y + __ldg(cols + e) * NCLS + c);
    float m = acc;
#pragma unroll
    for (int o = 4; o > 0; o >>= 1) m = fmaxf(m, __shfl_xor_sync(0xFFFFFFFFu, m, o));
    float ez = expf(acc - m);
    float s = ez;
#pragma unroll
    for (int o = 4; o > 0; o >>= 1) s += __shfl_xor_sync(0xFFFFFFFFu, s, o);
    out[row * NCLS + c] = ez / s;
}

// ---------------- launcher ---------------------------------------------------
extern "C" void kernel_launch(void* const* d_in, const int* in_sizes, int n_in,
                              void* d_out, int out_size) {
    const float* adj    = (const float*)d_in[0];
    const float* x      = (const float*)d_in[1];
    const float* gcn1_W = (const float*)d_in[2];
    const float* gcn1_b = (const float*)d_in[3];
    const float* Qw     = (const float*)d_in[4];
    const float* Qb     = (const float*)d_in[5];
    const float* Kw     = (const float*)d_in[6];
    const float* Kb     = (const float*)d_in[7];
    const float* Vw     = (const float*)d_in[8];
    const float* Vb     = (const float*)d_in[9];
    const float* ln_g   = (const float*)d_in[10];
    const float* ln_b   = (const float*)d_in[11];
    const float* gcn2_W = (const float*)d_in[12];
    const float* gcn2_b = (const float*)d_in[13];
    float* out = (float*)d_out;

    float *XW, *H, *Rp, *T, *Y, *M;
    cudaGetSymbolAddress((void**)&XW, g_XW);
    cudaGetSymbolAddress((void**)&H,  g_h);
    cudaGetSymbolAddress((void**)&Rp, g_R);
    cudaGetSymbolAddress((void**)&T,  g_V);
    cudaGetSymbolAddress((void**)&Y,  g_Y);
    cudaGetSymbolAddress((void**)&M,  g_N);

    static cudaStream_t s1 = nullptr;
    static cudaEvent_t evFork = nullptr, evPrep = nullptr, evM = nullptr,
                       evH = nullptr, evCs = nullptr;
    if (!s1) {
        cudaStreamCreateWithFlags(&s1, cudaStreamNonBlocking);
        cudaEventCreateWithFlags(&evFork, cudaEventDisableTiming);
        cudaEventCreateWithFlags(&evPrep, cudaEventDisableTiming);
        cudaEventCreateWithFlags(&evM,    cudaEventDisableTiming);
        cudaEventCreateWithFlags(&evH,    cudaEventDisableTiming);
        cudaEventCreateWithFlags(&evCs,   cudaEventDisableTiming);
    }

    dim3 gg(F / 128, NROWS / 128);

    // fork: build_ell (HBM) on stream 0 ∥ GEMM-prep on s1
    cudaEventRecord(evFork, 0);
    cudaStreamWaitEvent(s1, evFork, 0);

    build_ell<<<NROWS / 4, 128, 0, 0>>>(adj);

    sgemm512<<<gg, 256, 0, s1>>>(x, gcn1_W, nullptr, XW);
    uvc_kernel<<<129, 256, 0, s1>>>(Qw, Qb, Kw, Kb);
    cudaEventRecord(evPrep, s1);                          // join needs XW+u+v only
    gemm_abt512<<<dim3(8, 8), 256, 0, s1>>>(Qw, Kw, M);   // overlaps spmm on s0
    cudaEventRecord(evM, s1);

    cudaStreamWaitEvent(0, evPrep, 0);
    // join: needs ELL + XW + u + v
    spmm_relu_bav<<<NROWS, 128, 0, 0>>>(XW, gcn1_b, H);
    cudaEventRecord(evH, 0);

    // colsum on s1 (33 CTAs backfill beside the 256-CTA R'-GEMM wave)
    cudaStreamWaitEvent(s1, evH, 0);
    colsum_part<<<32, 512, 0, s1>>>(H);
    colsum_final<<<1, 512, 0, s1>>>();
    cudaEventRecord(evCs, s1);

    cudaStreamWaitEvent(0, evM, 0);
    sgemm512<<<gg, 256, 0, 0>>>(H, M, nullptr, Rp);       // R' = h @ M

    cudaStreamWaitEvent(0, evCs, 0);
    attn_fused<<<NROWS, 128, 0, 0>>>(H, Rp, XW);          // Xpre -> reuse g_XW

    sgemm512<<<gg, 256, 0, 0>>>(XW, Vw, Vb, T);           // T = Xpre@Vw + Vb
    ln_ygemm<<<NROWS, 128, 0, 0>>>(T, ln_g, ln_b, gcn2_W, Y);
    z_softmax<<<NROWS / 32, 256, 0, 0>>>(Y, gcn2_b, out);
}